// round 12
// baseline (speedup 1.0000x reference)
#include <cuda_runtime.h>
#include <cuda_fp16.h>
#include <cstdint>

// ---------------- problem constants ----------------
#define T_TOKENS 8192
#define HID      2048
#define NEXP     8
#define EDIM     1408
#define N1       (2*EDIM)            // 2816
#define NPAIR    (T_TOKENS*2)        // 16384
#define MAXTILES 136

// ---------------- GEMM tile config ----------------
// CTA tile: 128 (M) x 256 (tile cols) x 64 (K), 512 threads (16 warps, 4x4),
// warp tile 32 x 64. Legacy mma.sync fp16 (sm_103 PTX target has no tcgen05).
constexpr int BM = 128, BNT = 256, BK = 64, STAGES = 3;
constexpr int A_BYTES = BM * BK * 2;             // 16384
constexpr int B_BYTES = BK * BNT * 2;            // 32768
constexpr int STG_B   = A_BYTES + B_BYTES;       // 49152
constexpr int SMEM_BYTES = STAGES * STG_B;       // 147456

// ---------------- device scratch (static; no allocs) ----------------
__device__ __align__(16) __half g_x16 [(size_t)T_TOKENS * HID];        // 33.5 MB
__device__ __align__(16) __half g_up16[(size_t)NEXP * HID * N1];       // 92.3 MB [e][k][n]
__device__ __align__(16) __half g_dn16[(size_t)NEXP * EDIM * HID];     // 46.1 MB [e][k][n]
__device__ __align__(16) __half g_a   [(size_t)(NPAIR + 128) * EDIM];  // 46.4 MB (padded rows)
__device__ __align__(16) float  g_y   [(size_t)NPAIR * HID];           // 134 MB (per-pair y)
__device__ int    g_row_pair[NPAIR + 128];
__device__ int    g_cnt[NEXP];
__device__ int    g_cur[NEXP];
__device__ int    g_segstart[NEXP + 1];
__device__ int    g_tile_e   [MAXTILES];
__device__ int    g_tile_row0[MAXTILES];
__device__ int    g_tile_rows[MAXTILES];
__device__ int    g_is64;   // 1 if expert_indices buffer is int64, 0 if int32

// ---------------- PTX helpers ----------------
__device__ __forceinline__ void cp16(uint32_t dst, const void* src) {
    asm volatile("cp.async.cg.shared.global [%0], [%1], 16;\n" :: "r"(dst), "l"(src));
}
__device__ __forceinline__ void cp_commit() { asm volatile("cp.async.commit_group;\n"); }
__device__ __forceinline__ void ldsm4(uint32_t& r0, uint32_t& r1, uint32_t& r2, uint32_t& r3, uint32_t a) {
    asm volatile("ldmatrix.sync.aligned.m8n8.x4.shared.b16 {%0,%1,%2,%3}, [%4];"
                 : "=r"(r0), "=r"(r1), "=r"(r2), "=r"(r3) : "r"(a));
}
__device__ __forceinline__ void ldsm4t(uint32_t& r0, uint32_t& r1, uint32_t& r2, uint32_t& r3, uint32_t a) {
    asm volatile("ldmatrix.sync.aligned.m8n8.x4.trans.shared.b16 {%0,%1,%2,%3}, [%4];"
                 : "=r"(r0), "=r"(r1), "=r"(r2), "=r"(r3) : "r"(a));
}
__device__ __forceinline__ void mma16816(float* d, const uint32_t* a, const uint32_t* b) {
    asm volatile("mma.sync.aligned.m16n8k16.row.col.f32.f16.f16.f32 "
                 "{%0,%1,%2,%3}, {%4,%5,%6,%7}, {%8,%9}, {%0,%1,%2,%3};"
                 : "+f"(d[0]), "+f"(d[1]), "+f"(d[2]), "+f"(d[3])
                 : "r"(a[0]), "r"(a[1]), "r"(a[2]), "r"(a[3]), "r"(b[0]), "r"(b[1]));
}

// read expert index p under either dtype
__device__ __forceinline__ int read_eidx(const void* idx, int p) {
    if (g_is64) return (int)((const long long*)idx)[p];
    return ((const int*)idx)[p];
}

// ---------------- conversion kernels ----------------
__device__ __forceinline__ void cvt4(const float4* __restrict__ s, __half2* __restrict__ d, int i) {
    float4 v = s[i];
    d[2*i]   = __floats2half2_rn(v.x, v.y);
    d[2*i+1] = __floats2half2_rn(v.z, v.w);
}
__global__ void k_cvt_x (const float4* __restrict__ s) { cvt4(s, (__half2*)g_x16,  blockIdx.x*256 + threadIdx.x); }
__global__ void k_cvt_up(const float4* __restrict__ s) { cvt4(s, (__half2*)g_up16, blockIdx.x*256 + threadIdx.x); }
__global__ void k_cvt_dn(const float4* __restrict__ s) { cvt4(s, (__half2*)g_dn16, blockIdx.x*256 + threadIdx.x); }

// ---------------- routing kernels ----------------
// Dtype detection: values in [0,8). int64 little-endian => every odd 32-bit word is 0.
__global__ void k_route_init(const int* __restrict__ idx_words) {
    int t = threadIdx.x;
    if (t < NEXP) g_cnt[t] = 0;
    if (t == 0) {
        int any = 0;
        for (int i = 1; i < 256; i += 2) any |= idx_words[i];
        g_is64 = (any == 0) ? 1 : 0;
    }
}
__global__ void k_count(const void* __restrict__ idx) {
    int p = blockIdx.x * 256 + threadIdx.x;
    atomicAdd(&g_cnt[read_eidx(idx, p)], 1);
}
__global__ void k_scan() {
    int s = 0;
    for (int e = 0; e < NEXP; e++) { g_segstart[e] = s; s += g_cnt[e]; g_cur[e] = 0; }
    g_segstart[NEXP] = s;
    int t = 0;
    for (int e = 0; e < NEXP; e++) {
        int c = g_cnt[e];
        for (int off = 0; off < c; off += BM) {
            g_tile_e[t] = e;
            g_tile_row0[t] = g_segstart[e] + off;
            int rem = c - off;
            g_tile_rows[t] = rem < BM ? rem : BM;
            t++;
        }
    }
    for (; t < MAXTILES; t++) { g_tile_e[t] = -1; g_tile_row0[t] = 0; g_tile_rows[t] = 0; }
    for (int r = NPAIR; r < NPAIR + 128; r++) g_row_pair[r] = 0;
}
__global__ void k_scatter(const void* __restrict__ idx) {
    int p = blockIdx.x * 256 + threadIdx.x;
    int e = read_eidx(idx, p);
    int slot = atomicAdd(&g_cur[e], 1);
    g_row_pair[g_segstart[e] + slot] = p;
}

// ---------------- fused MoE GEMM (fp16 mma.sync, 3-stage cp.async) ----------------
// G1: A = gathered x16 rows (K=2048). B tile = 256 cols of up16[e], interleaved
//     8-col blocks: chunk cn even -> gate col n0+(cn>>1)*8, odd -> up col EDIM+n0+(cn>>1)*8.
//     Per-thread acc[j] (j even)=gate, acc[j+1]=up for SAME output cols ->
//     epilogue computes a = silu(gate)*up, writes fp16 g_a. 128 output cols/CTA.
// G2: A = g_a rows (K=1408), B = 256 contiguous cols of dn16[e].
//     Epilogue stores unscaled y[pair] rows fp32 (no atomics).
template<int KIT, int LDB, bool G1>
__global__ void __launch_bounds__(512, 1) moe_gemm(void) {
    int tile = blockIdx.y;
    int te = g_tile_e[tile];
    if (te < 0) return;
    int row0  = g_tile_row0[tile];
    int trows = g_tile_rows[tile];
    const __half* Bexp = (G1 ? g_up16 : g_dn16) + (size_t)te * (size_t)(KIT * BK) * LDB;

    extern __shared__ __half smem[];
    uint32_t sbase = (uint32_t)__cvta_generic_to_shared(smem);
    int tid = threadIdx.x;

    // per-thread load assignments: A 1024 chunks (2/thread), B 2048 chunks (4/thread)
    const __half* a_src[2]; uint32_t a_dst[2];
    const __half* b_src[4]; uint32_t b_dst[4];
#pragma unroll
    for (int i = 0; i < 2; i++) {
        int cid = tid + i * 512;
        int m = cid >> 3, c = cid & 7;                  // A: 128 rows x 8 chunks(16B)
        a_dst[i] = sbase + (uint32_t)(m * 128 + ((c ^ (m & 7)) << 4));
        if (G1) {
            int tok = g_row_pair[row0 + m] >> 1;        // pad rows -> pair 0 (in-bounds)
            a_src[i] = g_x16 + (size_t)tok * HID + c * 8;
        } else {
            a_src[i] = g_a + (size_t)(row0 + m) * EDIM + c * 8;  // padded scratch
        }
    }
#pragma unroll
    for (int i = 0; i < 4; i++) {
        int cid = tid + i * 512;
        int k = cid >> 5, cn = cid & 31;                // B: 64 rows x 32 chunks(16B)
        b_dst[i] = sbase + (uint32_t)(A_BYTES + k * 512 + ((cn ^ (k & 7)) << 4));
        int col;
        if (G1) {
            int n0 = blockIdx.x * 128;                  // output col base (gate index)
            col = ((cn & 1) ? EDIM : 0) + n0 + (cn >> 1) * 8;
        } else {
            col = blockIdx.x * 256 + cn * 8;
        }
        b_src[i] = Bexp + (size_t)k * LDB + col;
    }

    auto load_tile = [&](int stage, int kt) {
        uint32_t soff = (uint32_t)(stage * STG_B);
        int k0 = kt * BK;
#pragma unroll
        for (int i = 0; i < 2; i++) cp16(a_dst[i] + soff, a_src[i] + k0);
#pragma unroll
        for (int i = 0; i < 4; i++) cp16(b_dst[i] + soff, b_src[i] + (size_t)k0 * LDB);
    };

    int lane = tid & 31, warp = tid >> 5;
    int wm = (warp & 3) * 32;        // 4 warps along M (128)
    int wn = (warp >> 2) * 64;       // 4 warps along tile-N (256)
    int lr = lane & 15, lc = lane >> 4;

    float acc[2][8][4];
#pragma unroll
    for (int im = 0; im < 2; im++)
#pragma unroll
        for (int j = 0; j < 8; j++)
#pragma unroll
            for (int q = 0; q < 4; q++) acc[im][j][q] = 0.f;

    auto compute_stage = [&](int stage) {
        uint32_t abase = sbase + (uint32_t)(stage * STG_B);
        uint32_t bbase = abase + A_BYTES;
#pragma unroll
        for (int kk = 0; kk < 4; kk++) {               // 4 x k16 per BK=64
            uint32_t af[2][4], bf[8][2];
#pragma unroll
            for (int im = 0; im < 2; im++) {
                int m = wm + im * 16 + lr;
                int c = kk * 2 + lc;
                ldsm4(af[im][0], af[im][1], af[im][2], af[im][3],
                      abase + (uint32_t)(m * 128 + ((c ^ (m & 7)) << 4)));
            }
#pragma unroll
            for (int jn = 0; jn < 4; jn++) {
                int k = kk * 16 + lr;
                int c = ((wn + jn * 16) >> 3) + lc;
                ldsm4t(bf[2*jn][0], bf[2*jn][1], bf[2*jn+1][0], bf[2*jn+1][1],
                       bbase + (uint32_t)(k * 512 + ((c ^ (k & 7)) << 4)));
            }
#pragma unroll
            for (int im = 0; im < 2; im++)
#pragma unroll
                for (int j = 0; j < 8; j++)
                    mma16816(acc[im][j], af[im], bf[j]);
        }
    };

    // pipeline: prologue loads stages 0,1 (proven R10 structure)
    load_tile(0, 0); cp_commit();
    load_tile(1, 1); cp_commit();
#pragma unroll 1
    for (int kt = 0; kt < KIT; ++kt) {
        asm volatile("cp.async.wait_group 1;\n" ::: "memory");
        __syncthreads();
        if (kt + 2 < KIT) load_tile((kt + 2) % STAGES, kt + 2);
        cp_commit();
        compute_stage(kt % STAGES);
    }

    // epilogue
    int lq = lane >> 2;
    int ln = (lane & 3) * 2;
    if (G1) {
        int n0 = blockIdx.x * 128;
        int wno = (warp >> 2) * 32;                    // 32 output cols per warp
#pragma unroll
        for (int im = 0; im < 2; im++) {
#pragma unroll
            for (int rr = 0; rr < 2; rr++) {
                int rl = wm + im * 16 + lq + rr * 8;
                if (rl < trows) {
                    __half* dst = g_a + (size_t)(row0 + rl) * EDIM + n0 + wno;
#pragma unroll
                    for (int jh = 0; jh < 4; jh++) {   // bf pairs (2jh: gate, 2jh+1: up)
                        float g0 = acc[im][2*jh  ][2*rr], g1 = acc[im][2*jh  ][2*rr+1];
                        float u0 = acc[im][2*jh+1][2*rr], u1 = acc[im][2*jh+1][2*rr+1];
                        float v0 = g0 / (1.f + __expf(-g0)) * u0;
                        float v1 = g1 / (1.f + __expf(-g1)) * u1;
                        *reinterpret_cast<__half2*>(dst + jh * 8 + ln) = __floats2half2_rn(v0, v1);
                    }
                }
            }
        }
    } else {
        int n0 = blockIdx.x * 256;
#pragma unroll
        for (int im = 0; im < 2; im++) {
#pragma unroll
            for (int rr = 0; rr < 2; rr++) {
                int rl = wm + im * 16 + lq + rr * 8;
                if (rl < trows) {
                    int p = g_row_pair[row0 + rl];
                    float* dst = g_y + (size_t)p * HID + n0 + wn;
#pragma unroll
                    for (int j = 0; j < 8; j++) {
                        float2 v; v.x = acc[im][j][2*rr]; v.y = acc[im][j][2*rr+1];
                        *reinterpret_cast<float2*>(dst + j * 8 + ln) = v;
                    }
                }
            }
        }
    }
}

// ---------------- combine: out[t] = sc[2t]*y[2t] + sc[2t+1]*y[2t+1] ----------------
__global__ void k_combine(const float* __restrict__ sc, float4* __restrict__ out4) {
    int idx = blockIdx.x * 256 + threadIdx.x;   // T*HID/4
    int t = idx >> 9;                            // HID/4 = 512
    int j = idx & 511;
    const float4* y4 = (const float4*)g_y;
    float s0 = sc[2*t], s1 = sc[2*t + 1];
    float4 a = y4[(size_t)(2*t) * 512 + j];
    float4 b = y4[(size_t)(2*t + 1) * 512 + j];
    float4 o;
    o.x = s0 * a.x + s1 * b.x;
    o.y = s0 * a.y + s1 * b.y;
    o.z = s0 * a.z + s1 * b.z;
    o.w = s0 * a.w + s1 * b.w;
    out4[idx] = o;
}

// ---------------- host entry ----------------
extern "C" void kernel_launch(void* const* d_in, const int* in_sizes, int n_in,
                              void* d_out, int out_size) {
    const float* x    = (const float*)d_in[0];
    const void*  eidx = d_in[1];                 // int32 or int64 — detected on device
    const float* sc   = (const float*)d_in[2];
    const float* up   = (const float*)d_in[3];
    const float* dn   = (const float*)d_in[4];

    cudaFuncSetAttribute(moe_gemm<HID/BK,  N1,  true >, cudaFuncAttributeMaxDynamicSharedMemorySize, SMEM_BYTES);
    cudaFuncSetAttribute(moe_gemm<EDIM/BK, HID, false>, cudaFuncAttributeMaxDynamicSharedMemorySize, SMEM_BYTES);

    // fp32 -> fp16 conversions (native [e][k][n] weight layout — no transpose)
    k_cvt_x <<<(T_TOKENS*HID)  /4/256, 256>>>((const float4*)x);
    k_cvt_up<<<(NEXP*HID*N1)   /4/256, 256>>>((const float4*)up);
    k_cvt_dn<<<(NEXP*EDIM*HID) /4/256, 256>>>((const float4*)dn);

    // routing
    k_route_init<<<1, 32>>>((const int*)eidx);
    k_count  <<<NPAIR/256, 256>>>(eidx);
    k_scan   <<<1, 1>>>();
    k_scatter<<<NPAIR/256, 256>>>(eidx);

    // GEMM1 (fused SiLU): a = silu(x@up_gate) * (x@up_up), fp16  (11 x 136 CTAs)
    moe_gemm<HID/BK, N1, true><<<dim3(EDIM/128, MAXTILES), 512, SMEM_BYTES>>>();

    // GEMM2: y[pair] = a @ dn[e], fp32  (8 x 136 CTAs)
    moe_gemm<EDIM/BK, HID, false><<<dim3(HID/256, MAXTILES), 512, SMEM_BYTES>>>();

    // combine with scores
    k_combine<<<(T_TOKENS*HID)/4/256, 256>>>(sc, (float4*)d_out);

    (void)in_sizes; (void)n_in; (void)out_size;
}